// round 5
// baseline (speedup 1.0000x reference)
#include <cuda_runtime.h>
#include <cuda_bf16.h>

#define DD 16
#define LL 6
#define KK 64
#define BLOCK 256

typedef unsigned long long u64;

// Scratch: normalized mus in [l][k][d] pair-packed layout, folded alpha
// constants (c2' = -10*log2e*alpha + C1*pi^2/4), per-layer weights.
__device__ float4 g_mu[LL * KK * (DD / 4)];
__device__ float  g_c2p[LL * KK];
__device__ float  g_wv[LL];

#define C1_        (-7.2134752044448169f)   /* -5 * log2(e)          */
#define C2SCALE_   (-14.426950408889634f)   /* -10 * log2(e)         */
#define PI_        3.14159265358979323846f
#define HALF_PI_   1.5707963267948966f
#define LN2_TENTH  0.069314718055994531f    /* 0.1 * ln(2)           */
#define CLIP_      0.99999994f              /* fp32(1.0 - 1e-7)      */

__global__ void prep_kernel(const float* __restrict__ mus,
                            const float* __restrict__ alphas,
                            const float* __restrict__ ws) {
    int tid = threadIdx.x;
    if (tid < LL) {
        float w = ws[tid];
        g_wv[tid] = expf(-w * w);
    }
    if (tid >= LL * KK) return;
    int l = tid >> 6;
    int k = tid & 63;
    const float* m = mus + l * DD * KK + k;   // [L, D, K] layout
    float v[DD];
    float s = 0.f;
#pragma unroll
    for (int d = 0; d < DD; d++) {
        v[d] = m[d * KK];
        s += v[d] * v[d];
    }
    float inv = 1.0f / sqrtf(s);
    float* dst = reinterpret_cast<float*>(&g_mu[tid * 4]);
#pragma unroll
    for (int d = 0; d < DD; d++) dst[d] = v[d] * inv;
    // fold: c2' = C2SCALE*alpha + C1*(pi/2)^2
    g_c2p[tid] = C2SCALE_ * alphas[tid] + C1_ * (HALF_PI_ * HALF_PI_);
}

// ---------- fast scalar transcendentals ----------
__device__ __forceinline__ float fast_sqrt(float x) {
    float r; asm("sqrt.approx.f32 %0, %1;" : "=f"(r) : "f"(x)); return r;
}
__device__ __forceinline__ float fast_ex2(float x) {
    float r; asm("ex2.approx.f32 %0, %1;" : "=f"(r) : "f"(x)); return r;
}
__device__ __forceinline__ float fast_lg2(float x) {
    float r; asm("lg2.approx.f32 %0, %1;" : "=f"(r) : "f"(x)); return r;
}

// ---------- packed f32x2 ops ----------
__device__ __forceinline__ u64 fma2(u64 a, u64 b, u64 c) {
    u64 d; asm("fma.rn.f32x2 %0, %1, %2, %3;" : "=l"(d) : "l"(a), "l"(b), "l"(c)); return d;
}
__device__ __forceinline__ u64 mul2(u64 a, u64 b) {
    u64 d; asm("mul.rn.f32x2 %0, %1, %2;" : "=l"(d) : "l"(a), "l"(b)); return d;
}
__device__ __forceinline__ u64 add2(u64 a, u64 b) {
    u64 d; asm("add.rn.f32x2 %0, %1, %2;" : "=l"(d) : "l"(a), "l"(b)); return d;
}
__device__ __forceinline__ u64 pack2(float lo, float hi) {
    u64 d; asm("mov.b64 %0, {%1, %2};" : "=l"(d) : "f"(lo), "f"(hi)); return d;
}
__device__ __forceinline__ void unpack2(u64 v, float& lo, float& hi) {
    asm("mov.b64 {%0, %1}, %2;" : "=f"(lo), "=f"(hi) : "l"(v));
}

// packed dot of x (8 f32 pairs) with one mu row (8 f32 pairs in 4 ulonglong2)
__device__ __forceinline__ float dot16(const u64* xp,
                                       ulonglong2 m0, ulonglong2 m1,
                                       ulonglong2 m2, ulonglong2 m3) {
    u64 a = mul2(xp[0], m0.x);
    u64 b = mul2(xp[1], m0.y);
    a = fma2(xp[2], m1.x, a);
    b = fma2(xp[3], m1.y, b);
    a = fma2(xp[4], m2.x, a);
    b = fma2(xp[5], m2.y, b);
    a = fma2(xp[6], m3.x, a);
    b = fma2(xp[7], m3.y, b);
    u64 s = add2(a, b);
    float lo, hi;
    unpack2(s, lo, hi);
    return lo + hi;
}

__global__ __launch_bounds__(BLOCK, 6)
void main_kernel(const float* __restrict__ xs,
                 float* __restrict__ out,
                 int n_total) {
    __shared__ ulonglong2 s_mu[LL * KK * 4];   // 24 KB
    __shared__ float      s_c2[LL * KK];       // 1.5 KB (folded c2')
    __shared__ float      s_wv[LL];

    int tid = threadIdx.x;
    {
        const ulonglong2* gm = reinterpret_cast<const ulonglong2*>(g_mu);
        for (int i = tid; i < LL * KK * 4; i += BLOCK) s_mu[i] = gm[i];
        for (int i = tid; i < LL * KK; i += BLOCK) s_c2[i] = g_c2p[i];
        if (tid < LL) s_wv[tid] = g_wv[tid];
    }
    __syncthreads();

    int n = blockIdx.x * BLOCK + tid;
    if (n >= n_total) return;

    u64 xp[8];
    {
        const ulonglong2* xv = reinterpret_cast<const ulonglong2*>(xs + (size_t)n * DD);
        ulonglong2 v0 = xv[0], v1 = xv[1], v2 = xv[2], v3 = xv[3];
        xp[0] = v0.x; xp[1] = v0.y; xp[2] = v1.x; xp[3] = v1.y;
        xp[4] = v2.x; xp[5] = v2.y; xp[6] = v3.x; xp[7] = v3.y;
    }

    // Estrin even/odd packed acos-minimax constants:
    // acos(a)/sqrt(1-a) = E(a^2) + a*O(a^2); lanes = (even, odd) coeffs.
    const u64 K67 = pack2( 0.0066700901f, -0.0012624911f);  // (c6, c7)
    const u64 K45 = pack2( 0.0308918810f, -0.0170881256f);  // (c4, c5)
    const u64 K23 = pack2( 0.0889789874f, -0.0501743046f);  // (c2, c3)
    const u64 K01 = pack2( 1.5707963050f, -0.2145988016f);  // (c0, c1)
    const float Bc = -2.0f * C1_ * HALF_PI_;                 // folded dist^2 linear term

    float F = 0.f;
#pragma unroll 1
    for (int l = 0; l < LL; l++) {
        float sum0 = 0.f, sum1 = 0.f;
        const ulonglong2* mbase = s_mu + l * KK * 4;
        const float*      cbase = s_c2 + l * KK;
#pragma unroll 2
        for (int k = 0; k < KK; k++) {
            const ulonglong2* mb = mbase + k * 4;
            float dot = dot16(xp, mb[0], mb[1], mb[2], mb[3]);

            float a = fminf(fabsf(dot), CLIP_);   // single FMNMX |src|
            float z = a * a;
            u64 ZZ = pack2(z, z);
            u64 W = fma2(K67, ZZ, K45);
            W = fma2(W, ZZ, K23);
            W = fma2(W, ZZ, K01);
            float E, O;
            unpack2(W, E, O);
            float p = fmaf(a, O, E);

            float s  = fast_sqrt(1.0f - a);
            float dp = s * p;                      // acos(|dot|)
            // dist = pi/2 - copysign(pi/2 - dp, dot); arg = C1*dist^2 + c2
            // expanded: arg = (C1*c + B)*c + c2'   with c2' prefolded
            float c = copysignf(HALF_PI_ - dp, dot);
            float inner = fmaf(C1_, c, Bc);
            float arg = fmaf(inner, c, cbase[k]);
            if (k & 1) sum1 += fast_ex2(arg);
            else       sum0 += fast_ex2(arg);
        }
        float mincost = LN2_TENTH * fast_lg2(sum0 + sum1);
        float w = s_wv[l];
        F = fmaf(w, fmaxf(F, 0.f), (1.0f - w) * mincost);
    }

    // smooth min(F, 0): 0.1 * log(1 + exp(-10F))
    float s = fast_ex2(C2SCALE_ * F);
    out[n] = 0.1f * log1pf(s);
}

extern "C" void kernel_launch(void* const* d_in, const int* in_sizes, int n_in,
                              void* d_out, int out_size) {
    const float* xs     = (const float*)d_in[0];
    const float* mus    = (const float*)d_in[1];
    const float* alphas = (const float*)d_in[2];
    const float* ws     = (const float*)d_in[3];
    float* out = (float*)d_out;

    int n_total = in_sizes[0] / DD;

    prep_kernel<<<1, LL * KK>>>(mus, alphas, ws);
    int blocks = (n_total + BLOCK - 1) / BLOCK;
    main_kernel<<<blocks, BLOCK>>>(xs, out, n_total);
}